// round 10
// baseline (speedup 1.0000x reference)
#include <cuda_runtime.h>
#include <cuda_bf16.h>
#include <cstdint>
#include <math.h>

// phi (64,256) row-major, X (256,K), Y (64,K); k = idx+1 active columns.
constexpr int NROW = 256;
constexpr int MDIM = 64;
constexpr int NT   = 128;   // columns per CTA tile
constexpr int TPB  = 256;   // 8 warps

// ---- SMEM map ----
constexpr int PHA_HI = 0;       // phi [64][264] bf16 row-major (k-contig), 528B row stride
constexpr int PHA_LO = 33792;
constexpr int POOL   = 67584;
constexpr int XSBUF  = 20480;   // double-buffered X chunk (hi at +0, lo at +10240)
constexpr int RS_HI  = POOL;    // resid [128 cols][36 u32]; aliases XS (time-disjoint)
constexpr int RS_LO  = POOL + 18432;
constexpr int SMEM_TOTAL = POOL + 40960 + 128;   // 108672

constexpr int PHA_SB = 528;
constexpr int XS_SB  = 80;     // 5 x 16B per col -> STS.128 conflict-free (5 coprime 8)
constexpr int RS_S32 = 36;
constexpr int RS_SB  = 144;

constexpr int CHUNK = 32;
constexpr int NCHUNK = NROW / CHUNK;  // 8

__device__ __forceinline__ void bf16_split(float v, uint16_t& hi, uint16_t& lo) {
    __nv_bfloat16 h = __float2bfloat16_rn(v);
    __nv_bfloat16 l = __float2bfloat16_rn(v - __bfloat162float(h));
    hi = __bfloat16_as_ushort(h);
    lo = __bfloat16_as_ushort(l);
}
__device__ __forceinline__ uint32_t smem_u32(const void* p) {
    uint32_t a;
    asm("{ .reg .u64 t; cvta.to.shared.u64 t, %1; cvt.u32.u64 %0, t; }" : "=r"(a) : "l"(p));
    return a;
}

#define MMA_BF16(c, a, b0, b1)                                                  \
    asm volatile("mma.sync.aligned.m16n8k16.row.col.f32.bf16.bf16.f32 "         \
        "{%0,%1,%2,%3}, {%4,%5,%6,%7}, {%8,%9}, {%0,%1,%2,%3};"                 \
        : "+f"((c)[0]), "+f"((c)[1]), "+f"((c)[2]), "+f"((c)[3])                \
        : "r"((a)[0]), "r"((a)[1]), "r"((a)[2]), "r"((a)[3]), "r"(b0), "r"(b1))

#define LDMX4(r, addr)                                                          \
    asm volatile("ldmatrix.sync.aligned.m8n8.x4.shared.b16 {%0,%1,%2,%3}, [%4];"\
        : "=r"((r)[0]), "=r"((r)[1]), "=r"((r)[2]), "=r"((r)[3]) : "r"(addr))
#define LDMX4T(r, addr)                                                         \
    asm volatile("ldmatrix.sync.aligned.m8n8.x4.trans.shared.b16 {%0,%1,%2,%3}, [%4];" \
        : "=r"((r)[0]), "=r"((r)[1]), "=r"((r)[2]), "=r"((r)[3]) : "r"(addr))
#define LDMX2(r, addr)                                                          \
    asm volatile("ldmatrix.sync.aligned.m8n8.x2.shared.b16 {%0,%1}, [%2];"      \
        : "=r"((r)[0]), "=r"((r)[1]) : "r"(addr))

extern __shared__ char smem[];

__global__ __launch_bounds__(TPB, 2)
void ista_hmma_kernel(const float* __restrict__ phi,
                      const float* __restrict__ X,
                      const float* __restrict__ Y,
                      const float* __restrict__ step,
                      const int*   __restrict__ idxp,
                      float*       __restrict__ outX,
                      int K)
{
    const int tid  = threadIdx.x;
    const int w    = tid >> 5;
    const int lane = tid & 31;
    const int g    = lane >> 2;
    const int tg   = lane & 3;
    const int base = blockIdx.x * NT;
    const int kact = *idxp + 1;

    if (base >= kact) {
        const int col = base + (tid & 127);
        if (col < K) {
            for (int n = (tid >> 7); n < NROW; n += 2)
                outX[(size_t)n * K + col] = X[(size_t)n * K + col];
        }
        return;
    }

    const float s = *step;

    uint32_t* pha_hi = (uint32_t*)(smem + PHA_HI);
    uint32_t* pha_lo = (uint32_t*)(smem + PHA_LO);
    uint16_t* rs_hi16 = (uint16_t*)(smem + RS_HI);
    uint16_t* rs_lo16 = (uint16_t*)(smem + RS_LO);

    const uint32_t pha_hi_b = smem_u32(smem + PHA_HI);
    const uint32_t pha_lo_b = smem_u32(smem + PHA_LO);
    const uint32_t pool_b   = smem_u32(smem + POOL);
    const uint32_t rs_hi_b  = smem_u32(smem + RS_HI);
    const uint32_t rs_lo_b  = smem_u32(smem + RS_LO);

    // staging geometry: thread covers col = tid&127, k-quads {qb, qb+1} (each = 8 X rows)
    const int scol = tid & 127;
    const int qb   = (tid >> 7) * 2;
    int gc = base + scol; gc = (gc < K) ? gc : (K - 1);

    // 2-deep register pipeline of X chunks: xr[buf][local quad][j] = rows (2j, 2j+1)
    float2 xr[2][2][4];
    #pragma unroll
    for (int lq = 0; lq < 2; ++lq)
        #pragma unroll
        for (int j = 0; j < 4; ++j) {
            const int r = (qb + lq) * 8 + 2 * j;   // chunk 0
            xr[0][lq][j].x = X[(size_t)r * K + gc];
            xr[0][lq][j].y = X[(size_t)(r + 1) * K + gc];
        }

    // ---------------- stage phi (hi/lo splits, native row-major) ----------------
    for (int it = tid; it < MDIM * 128; it += TPB) {
        const int m = it >> 7, kp = it & 127;
        const float2 v = *(const float2*)(phi + m * NROW + 2 * kp);
        uint16_t h0, l0, h1, l1;
        bf16_split(v.x, h0, l0);
        bf16_split(v.y, h1, l1);
        pha_hi[m * 132 + kp] = (uint32_t)h0 | ((uint32_t)h1 << 16);
        pha_lo[m * 132 + kp] = (uint32_t)l0 | ((uint32_t)l1 << 16);
    }

    // chunk 1 into pipeline slot 1
    #pragma unroll
    for (int lq = 0; lq < 2; ++lq)
        #pragma unroll
        for (int j = 0; j < 4; ++j) {
            const int r = CHUNK + (qb + lq) * 8 + 2 * j;
            xr[1][lq][j].x = X[(size_t)r * K + gc];
            xr[1][lq][j].y = X[(size_t)(r + 1) * K + gc];
        }

    // ================= GEMM A: R(64x128) = phi . Xtile =================
    const int mbase = 32 * (w & 1);
    const int nbase = 32 * (w >> 1);
    float cA[2][4][4];
    #pragma unroll
    for (int mt = 0; mt < 2; ++mt)
        #pragma unroll
        for (int nt = 0; nt < 4; ++nt)
            #pragma unroll
            for (int q = 0; q < 4; ++q) cA[mt][nt][q] = 0.0f;

    const uint32_t a_row_off = (uint32_t)(lane & 15) * PHA_SB + (uint32_t)((lane >> 4) << 3) * 2;
    const uint32_t b_row     = (uint32_t)(lane & 7);
    const uint32_t b_koff    = (uint32_t)(((lane >> 3) & 1) << 3) * 2;

    float2 yv[2][4][2];

    #pragma unroll 1
    for (int chunk = 0; chunk < NCHUNK; ++chunk) {
        const int buf = chunk & 1;
        const uint32_t xb = pool_b + (uint32_t)buf * XSBUF;

        // STS.128 current chunk (conflict-free: 16B addr = scol*5 + q, 5 coprime 8)
        #pragma unroll
        for (int lq = 0; lq < 2; ++lq) {
            uint32_t hi[4], lo[4];
            #pragma unroll
            for (int j = 0; j < 4; ++j) {
                uint16_t h0, l0, h1, l1;
                bf16_split(xr[buf][lq][j].x, h0, l0);
                bf16_split(xr[buf][lq][j].y, h1, l1);
                hi[j] = (uint32_t)h0 | ((uint32_t)h1 << 16);
                lo[j] = (uint32_t)l0 | ((uint32_t)l1 << 16);
            }
            char* p = smem + POOL + buf * XSBUF + scol * XS_SB + (qb + lq) * 16;
            *(uint4*)p           = make_uint4(hi[0], hi[1], hi[2], hi[3]);
            *(uint4*)(p + 10240) = make_uint4(lo[0], lo[1], lo[2], lo[3]);
        }

        // refill pipeline: chunk+2 (or Y at the end) — ~2 chunk-times of latency cover
        if (chunk + 2 < NCHUNK) {
            #pragma unroll
            for (int lq = 0; lq < 2; ++lq)
                #pragma unroll
                for (int j = 0; j < 4; ++j) {
                    const int r = (chunk + 2) * CHUNK + (qb + lq) * 8 + 2 * j;
                    xr[buf][lq][j].x = X[(size_t)r * K + gc];
                    xr[buf][lq][j].y = X[(size_t)(r + 1) * K + gc];
                }
        } else if (chunk + 2 == NCHUNK) {
            #pragma unroll
            for (int mt = 0; mt < 2; ++mt)
                #pragma unroll
                for (int nt = 0; nt < 4; ++nt) {
                    const int nloc = nbase + nt * 8 + 2 * tg;
                    int col0 = base + nloc; col0 = (col0 < K - 1) ? col0 : (K - 2);
                    const int m0 = mbase + 16 * mt + g;
                    yv[mt][nt][0] = *(const float2*)(Y + (size_t)m0 * K + col0);
                    yv[mt][nt][1] = *(const float2*)(Y + (size_t)(m0 + 8) * K + col0);
                }
        }
        __syncthreads();

        // MMA this chunk (2 k-steps of 16)
        #pragma unroll
        for (int ks = 0; ks < 2; ++ks) {
            const int k0 = chunk * CHUNK + ks * 16;
            uint32_t ah[2][4], al[2][4];
            #pragma unroll
            for (int mt = 0; mt < 2; ++mt) {
                const uint32_t aoff = (uint32_t)(mbase + 16 * mt) * PHA_SB
                                    + (uint32_t)k0 * 2 + a_row_off;
                LDMX4(ah[mt], pha_hi_b + aoff);
                LDMX4(al[mt], pha_lo_b + aoff);
            }
            #pragma unroll
            for (int nt = 0; nt < 4; ++nt) {
                const uint32_t roff = (uint32_t)(nbase + nt * 8 + b_row) * XS_SB
                                    + (uint32_t)(ks * 16) * 2 + b_koff;
                uint32_t bh[2], bl[2];
                LDMX2(bh, xb + roff);
                LDMX2(bl, xb + 10240 + roff);
                #pragma unroll
                for (int mt = 0; mt < 2; ++mt) {
                    MMA_BF16(cA[mt][nt], ah[mt], bh[0], bh[1]);
                    MMA_BF16(cA[mt][nt], ah[mt], bl[0], bl[1]);
                    MMA_BF16(cA[mt][nt], al[mt], bh[0], bh[1]);
                }
            }
        }
    }
    __syncthreads();   // all MMA reads of pool done before RS aliases it

    // ---- epilogue A: r = s*(y - R) -> bf16 split -> Rs[n][m] ----
    #pragma unroll
    for (int mt = 0; mt < 2; ++mt)
        #pragma unroll
        for (int nt = 0; nt < 4; ++nt) {
            const int nloc = nbase + nt * 8 + 2 * tg;
            const int m0 = mbase + 16 * mt + g, m1 = m0 + 8;
            const float2 y0 = yv[mt][nt][0], y1 = yv[mt][nt][1];
            const float r00 = s * (y0.x - cA[mt][nt][0]);
            const float r01 = s * (y0.y - cA[mt][nt][1]);
            const float r10 = s * (y1.x - cA[mt][nt][2]);
            const float r11 = s * (y1.y - cA[mt][nt][3]);
            uint16_t h, l;
            bf16_split(r00, h, l); rs_hi16[nloc * 72 + m0] = h; rs_lo16[nloc * 72 + m0] = l;
            bf16_split(r01, h, l); rs_hi16[(nloc + 1) * 72 + m0] = h; rs_lo16[(nloc + 1) * 72 + m0] = l;
            bf16_split(r10, h, l); rs_hi16[nloc * 72 + m1] = h; rs_lo16[nloc * 72 + m1] = l;
            bf16_split(r11, h, l); rs_hi16[(nloc + 1) * 72 + m1] = h; rs_lo16[(nloc + 1) * 72 + m1] = l;
        }
    __syncthreads();

    // ================= GEMM B: corr(256x128) = phiT . R, K=64 =================
    const int lrow = (lane & 7) + ((lane & 16) >> 1);
    const int lcol = (lane & 8);

    #pragma unroll 1
    for (int pass = 0; pass < 2; ++pass) {
        const int nb = pass * 64;
        float cB[2][8][4];
        #pragma unroll
        for (int mt = 0; mt < 2; ++mt)
            #pragma unroll
            for (int nt = 0; nt < 8; ++nt)
                #pragma unroll
                for (int q = 0; q < 4; ++q) cB[mt][nt][q] = 0.0f;

        #pragma unroll
        for (int ks = 0; ks < 4; ++ks) {
            const int k0 = ks * 16;
            uint32_t ath[2][4], atl[2][4];
            #pragma unroll
            for (int mt = 0; mt < 2; ++mt) {
                const int m0 = 32 * w + 16 * mt;
                const uint32_t off = (uint32_t)((k0 + lrow) * PHA_SB + (m0 + lcol) * 2);
                LDMX4T(ath[mt], pha_hi_b + off);
                LDMX4T(atl[mt], pha_lo_b + off);
            }
            #pragma unroll
            for (int nt = 0; nt < 8; ++nt) {
                const uint32_t roff = (uint32_t)(nb + nt * 8 + b_row) * RS_SB
                                    + (uint32_t)(ks * 16) * 2 + b_koff;
                uint32_t bh[2], bl[2];
                LDMX2(bh, rs_hi_b + roff);
                LDMX2(bl, rs_lo_b + roff);
                #pragma unroll
                for (int mt = 0; mt < 2; ++mt) {
                    MMA_BF16(cB[mt][nt], ath[mt], bh[0], bh[1]);
                    MMA_BF16(cB[mt][nt], ath[mt], bl[0], bl[1]);
                    MMA_BF16(cB[mt][nt], atl[mt], bh[0], bh[1]);
                }
            }
        }

        #pragma unroll
        for (int mt = 0; mt < 2; ++mt) {
            #pragma unroll
            for (int nt = 0; nt < 8; ++nt) {
                const int col0 = base + nb + nt * 8 + 2 * tg;
                if (col0 + 1 >= K) continue;
                const int r0 = 32 * w + 16 * mt + g;
                const int r1 = r0 + 8;
                const float2 x0 = *(const float2*)(X + (size_t)r0 * K + col0);
                const float2 x1 = *(const float2*)(X + (size_t)r1 * K + col0);
                float u00 = x0.x + cB[mt][nt][0];
                float u01 = x0.y + cB[mt][nt][1];
                float u10 = x1.x + cB[mt][nt][2];
                float u11 = x1.y + cB[mt][nt][3];
                u00 = (fabsf(u00) > 0.1f) ? u00 : 0.0f;
                u01 = (fabsf(u01) > 0.1f) ? u01 : 0.0f;
                u10 = (fabsf(u10) > 0.1f) ? u10 : 0.0f;
                u11 = (fabsf(u11) > 0.1f) ? u11 : 0.0f;
                const bool a0 = (col0 < kact), a1 = (col0 + 1 < kact);
                float2 o0, o1;
                o0.x = a0 ? u00 : x0.x;  o0.y = a1 ? u01 : x0.y;
                o1.x = a0 ? u10 : x1.x;  o1.y = a1 ? u11 : x1.y;
                *(float2*)(outX + (size_t)r0 * K + col0) = o0;
                *(float2*)(outX + (size_t)r1 * K + col0) = o1;
            }
        }
    }
}

extern "C" void kernel_launch(void* const* d_in, const int* in_sizes, int n_in,
                              void* d_out, int out_size)
{
    const float* phi  = (const float*)d_in[0];
    const float* X    = (const float*)d_in[1];
    const float* Y    = (const float*)d_in[2];
    const float* step = (const float*)d_in[3];
    const int*   idx  = (const int*)d_in[4];

    const int phiN = in_sizes[0];
    const int XN   = in_sizes[1];
    const int K    = XN / NROW;

    float* outX = (float*)d_out;
    if (out_size == phiN + XN) {
        cudaMemcpyAsync(d_out, phi, (size_t)phiN * sizeof(float),
                        cudaMemcpyDeviceToDevice, 0);
        outX = (float*)d_out + phiN;
    }

    cudaFuncSetAttribute(ista_hmma_kernel,
                         cudaFuncAttributeMaxDynamicSharedMemorySize, SMEM_TOTAL);

    const int grid = (K + NT - 1) / NT;
    ista_hmma_kernel<<<grid, TPB, SMEM_TOTAL>>>(phi, X, Y, step, idx, outX, K);
}

// round 11
// speedup vs baseline: 1.1122x; 1.1122x over previous
#include <cuda_runtime.h>
#include <cuda_bf16.h>
#include <cstdint>
#include <math.h>

// phi (64,256) row-major, X (256,K), Y (64,K); k = idx+1 active columns.
constexpr int NROW = 256;
constexpr int MDIM = 64;
constexpr int NT   = 128;   // columns per CTA tile
constexpr int TPB  = 256;   // 8 warps

// ---- SMEM map ----
constexpr int PHA_HI = 0;       // phi [64][264] bf16 row-major (k-contig), 528B row stride
constexpr int PHA_LO = 33792;
constexpr int POOL   = 67584;
constexpr int XSBUF  = 20480;   // double-buffered X chunk (hi at +0, lo at +10240)
constexpr int RS_HI  = POOL;    // resid [128 cols][36 u32]; aliases XS (time-disjoint)
constexpr int RS_LO  = POOL + 18432;
constexpr int SMEM_TOTAL = POOL + 40960 + 128;   // 108672

constexpr int PHA_SB = 528;
constexpr int XS_SB  = 80;     // 5 x 16B per col -> STS.128 conflict-free (5 coprime 8)
constexpr int RS_SB  = 144;

constexpr int CHUNK = 32;
constexpr int NCHUNK = NROW / CHUNK;  // 8

__device__ __forceinline__ void bf16_split(float v, uint16_t& hi, uint16_t& lo) {
    __nv_bfloat16 h = __float2bfloat16_rn(v);
    __nv_bfloat16 l = __float2bfloat16_rn(v - __bfloat162float(h));
    hi = __bfloat16_as_ushort(h);
    lo = __bfloat16_as_ushort(l);
}
__device__ __forceinline__ uint32_t smem_u32(const void* p) {
    uint32_t a;
    asm("{ .reg .u64 t; cvta.to.shared.u64 t, %1; cvt.u32.u64 %0, t; }" : "=r"(a) : "l"(p));
    return a;
}

#define MMA_BF16(c, a, b0, b1)                                                  \
    asm volatile("mma.sync.aligned.m16n8k16.row.col.f32.bf16.bf16.f32 "         \
        "{%0,%1,%2,%3}, {%4,%5,%6,%7}, {%8,%9}, {%0,%1,%2,%3};"                 \
        : "+f"((c)[0]), "+f"((c)[1]), "+f"((c)[2]), "+f"((c)[3])                \
        : "r"((a)[0]), "r"((a)[1]), "r"((a)[2]), "r"((a)[3]), "r"(b0), "r"(b1))

#define LDMX4(r, addr)                                                          \
    asm volatile("ldmatrix.sync.aligned.m8n8.x4.shared.b16 {%0,%1,%2,%3}, [%4];"\
        : "=r"((r)[0]), "=r"((r)[1]), "=r"((r)[2]), "=r"((r)[3]) : "r"(addr))
#define LDMX4T(r, addr)                                                         \
    asm volatile("ldmatrix.sync.aligned.m8n8.x4.trans.shared.b16 {%0,%1,%2,%3}, [%4];" \
        : "=r"((r)[0]), "=r"((r)[1]), "=r"((r)[2]), "=r"((r)[3]) : "r"(addr))
#define LDMX2(r, addr)                                                          \
    asm volatile("ldmatrix.sync.aligned.m8n8.x2.shared.b16 {%0,%1}, [%2];"      \
        : "=r"((r)[0]), "=r"((r)[1]) : "r"(addr))

extern __shared__ char smem_g[];

// ---- helpers with ONLY compile-time register indexing ----
__device__ __forceinline__ void refill_chunk(const float* __restrict__ X, int chunk,
                                             int qb, int gc, int K, float2 (&xr)[2][4]) {
    #pragma unroll
    for (int lq = 0; lq < 2; ++lq)
        #pragma unroll
        for (int j = 0; j < 4; ++j) {
            const int r = chunk * CHUNK + (qb + lq) * 8 + 2 * j;
            xr[lq][j].x = X[(size_t)r * K + gc];
            xr[lq][j].y = X[(size_t)(r + 1) * K + gc];
        }
}

__device__ __forceinline__ void sts_chunk(char* smem, int bufoff, int scol, int qb,
                                          const float2 (&xr)[2][4]) {
    #pragma unroll
    for (int lq = 0; lq < 2; ++lq) {
        uint32_t hi[4], lo[4];
        #pragma unroll
        for (int j = 0; j < 4; ++j) {
            uint16_t h0, l0, h1, l1;
            bf16_split(xr[lq][j].x, h0, l0);
            bf16_split(xr[lq][j].y, h1, l1);
            hi[j] = (uint32_t)h0 | ((uint32_t)h1 << 16);
            lo[j] = (uint32_t)l0 | ((uint32_t)l1 << 16);
        }
        char* p = smem + POOL + bufoff + scol * XS_SB + (qb + lq) * 16;
        *(uint4*)p           = make_uint4(hi[0], hi[1], hi[2], hi[3]);
        *(uint4*)(p + 10240) = make_uint4(lo[0], lo[1], lo[2], lo[3]);
    }
}

__device__ __forceinline__ void mma_chunk(int chunk, uint32_t xb,
                                          uint32_t pha_hi_b, uint32_t pha_lo_b,
                                          int mbase, int nbase,
                                          uint32_t a_row_off, uint32_t b_row, uint32_t b_koff,
                                          float (&cA)[2][4][4]) {
    #pragma unroll
    for (int ks = 0; ks < 2; ++ks) {
        const int k0 = chunk * CHUNK + ks * 16;
        uint32_t ah[2][4], al[2][4];
        #pragma unroll
        for (int mt = 0; mt < 2; ++mt) {
            const uint32_t aoff = (uint32_t)(mbase + 16 * mt) * PHA_SB
                                + (uint32_t)k0 * 2 + a_row_off;
            LDMX4(ah[mt], pha_hi_b + aoff);
            LDMX4(al[mt], pha_lo_b + aoff);
        }
        #pragma unroll
        for (int nt = 0; nt < 4; ++nt) {
            const uint32_t roff = (uint32_t)(nbase + nt * 8 + b_row) * XS_SB
                                + (uint32_t)(ks * 16) * 2 + b_koff;
            uint32_t bh[2], bl[2];
            LDMX2(bh, xb + roff);
            LDMX2(bl, xb + 10240 + roff);
            #pragma unroll
            for (int mt = 0; mt < 2; ++mt) {
                MMA_BF16(cA[mt][nt], ah[mt], bh[0], bh[1]);
                MMA_BF16(cA[mt][nt], ah[mt], bl[0], bl[1]);
                MMA_BF16(cA[mt][nt], al[mt], bh[0], bh[1]);
            }
        }
    }
}

__global__ __launch_bounds__(TPB, 2)
void ista_hmma_kernel(const float* __restrict__ phi,
                      const float* __restrict__ X,
                      const float* __restrict__ Y,
                      const float* __restrict__ step,
                      const int*   __restrict__ idxp,
                      float*       __restrict__ outX,
                      int K)
{
    char* smem = smem_g;
    const int tid  = threadIdx.x;
    const int w    = tid >> 5;
    const int lane = tid & 31;
    const int g    = lane >> 2;
    const int tg   = lane & 3;
    const int base = blockIdx.x * NT;
    const int kact = *idxp + 1;

    if (base >= kact) {
        const int col = base + (tid & 127);
        if (col < K) {
            for (int n = (tid >> 7); n < NROW; n += 2)
                outX[(size_t)n * K + col] = X[(size_t)n * K + col];
        }
        return;
    }

    const float s = *step;

    uint32_t* pha_hi = (uint32_t*)(smem + PHA_HI);
    uint32_t* pha_lo = (uint32_t*)(smem + PHA_LO);
    uint16_t* rs_hi16 = (uint16_t*)(smem + RS_HI);
    uint16_t* rs_lo16 = (uint16_t*)(smem + RS_LO);

    const uint32_t pha_hi_b = smem_u32(smem + PHA_HI);
    const uint32_t pha_lo_b = smem_u32(smem + PHA_LO);
    const uint32_t pool_b   = smem_u32(smem + POOL);
    const uint32_t rs_hi_b  = smem_u32(smem + RS_HI);
    const uint32_t rs_lo_b  = smem_u32(smem + RS_LO);

    // staging geometry: thread covers col = tid&127, k-quads {qb, qb+1}
    const int scol = tid & 127;
    const int qb   = (tid >> 7) * 2;
    int gc = base + scol; gc = (gc < K) ? gc : (K - 1);

    // two FLAT register pipelines (no dynamic indexing -> no spills)
    float2 xrA[2][4], xrB[2][4];
    refill_chunk(X, 0, qb, gc, K, xrA);   // chunk-0 LDGs hide under phi staging

    // ---------------- stage phi (hi/lo splits, native row-major) ----------------
    for (int it = tid; it < MDIM * 128; it += TPB) {
        const int m = it >> 7, kp = it & 127;
        const float2 v = *(const float2*)(phi + m * NROW + 2 * kp);
        uint16_t h0, l0, h1, l1;
        bf16_split(v.x, h0, l0);
        bf16_split(v.y, h1, l1);
        pha_hi[m * 132 + kp] = (uint32_t)h0 | ((uint32_t)h1 << 16);
        pha_lo[m * 132 + kp] = (uint32_t)l0 | ((uint32_t)l1 << 16);
    }
    refill_chunk(X, 1, qb, gc, K, xrB);

    // ================= GEMM A: R(64x128) = phi . Xtile =================
    const int mbase = 32 * (w & 1);
    const int nbase = 32 * (w >> 1);
    float cA[2][4][4];
    #pragma unroll
    for (int mt = 0; mt < 2; ++mt)
        #pragma unroll
        for (int nt = 0; nt < 4; ++nt)
            #pragma unroll
            for (int q = 0; q < 4; ++q) cA[mt][nt][q] = 0.0f;

    const uint32_t a_row_off = (uint32_t)(lane & 15) * PHA_SB + (uint32_t)((lane >> 4) << 3) * 2;
    const uint32_t b_row     = (uint32_t)(lane & 7);
    const uint32_t b_koff    = (uint32_t)(((lane >> 3) & 1) << 3) * 2;

    float2 yv[2][4][2];

    #pragma unroll 1
    for (int cp = 0; cp < 4; ++cp) {
        const int c0 = 2 * cp, c1 = 2 * cp + 1;

        // ---- buffer 0 / even chunk ----
        sts_chunk(smem, 0, scol, qb, xrA);
        if (c0 + 2 < NCHUNK) {
            refill_chunk(X, c0 + 2, qb, gc, K, xrA);
        } else {   // cp == 3: prefetch Y for epilogue A instead
            #pragma unroll
            for (int mt = 0; mt < 2; ++mt)
                #pragma unroll
                for (int nt = 0; nt < 4; ++nt) {
                    const int nloc = nbase + nt * 8 + 2 * tg;
                    int col0 = base + nloc; col0 = (col0 < K - 1) ? col0 : (K - 2);
                    const int m0 = mbase + 16 * mt + g;
                    yv[mt][nt][0] = *(const float2*)(Y + (size_t)m0 * K + col0);
                    yv[mt][nt][1] = *(const float2*)(Y + (size_t)(m0 + 8) * K + col0);
                }
        }
        __syncthreads();
        mma_chunk(c0, pool_b, pha_hi_b, pha_lo_b, mbase, nbase,
                  a_row_off, b_row, b_koff, cA);

        // ---- buffer 1 / odd chunk ----
        sts_chunk(smem, XSBUF, scol, qb, xrB);
        if (c1 + 2 < NCHUNK)
            refill_chunk(X, c1 + 2, qb, gc, K, xrB);
        __syncthreads();
        mma_chunk(c1, pool_b + XSBUF, pha_hi_b, pha_lo_b, mbase, nbase,
                  a_row_off, b_row, b_koff, cA);
    }
    __syncthreads();   // all MMA reads of pool done before RS aliases it

    // ---- epilogue A: r = s*(y - R) -> bf16 split -> Rs[n][m] ----
    #pragma unroll
    for (int mt = 0; mt < 2; ++mt)
        #pragma unroll
        for (int nt = 0; nt < 4; ++nt) {
            const int nloc = nbase + nt * 8 + 2 * tg;
            const int m0 = mbase + 16 * mt + g, m1 = m0 + 8;
            const float2 y0 = yv[mt][nt][0], y1 = yv[mt][nt][1];
            const float r00 = s * (y0.x - cA[mt][nt][0]);
            const float r01 = s * (y0.y - cA[mt][nt][1]);
            const float r10 = s * (y1.x - cA[mt][nt][2]);
            const float r11 = s * (y1.y - cA[mt][nt][3]);
            uint16_t h, l;
            bf16_split(r00, h, l); rs_hi16[nloc * 72 + m0] = h; rs_lo16[nloc * 72 + m0] = l;
            bf16_split(r01, h, l); rs_hi16[(nloc + 1) * 72 + m0] = h; rs_lo16[(nloc + 1) * 72 + m0] = l;
            bf16_split(r10, h, l); rs_hi16[nloc * 72 + m1] = h; rs_lo16[nloc * 72 + m1] = l;
            bf16_split(r11, h, l); rs_hi16[(nloc + 1) * 72 + m1] = h; rs_lo16[(nloc + 1) * 72 + m1] = l;
        }
    __syncthreads();

    // ================= GEMM B: corr(256x128) = phiT . R, K=64 =================
    const int lrow = (lane & 7) + ((lane & 16) >> 1);
    const int lcol = (lane & 8);

    #pragma unroll 1
    for (int pass = 0; pass < 2; ++pass) {
        const int nb = pass * 64;
        float cB[2][8][4];
        #pragma unroll
        for (int mt = 0; mt < 2; ++mt)
            #pragma unroll
            for (int nt = 0; nt < 8; ++nt)
                #pragma unroll
                for (int q = 0; q < 4; ++q) cB[mt][nt][q] = 0.0f;

        #pragma unroll
        for (int ks = 0; ks < 4; ++ks) {
            const int k0 = ks * 16;
            uint32_t ath[2][4], atl[2][4];
            #pragma unroll
            for (int mt = 0; mt < 2; ++mt) {
                const int m0 = 32 * w + 16 * mt;
                const uint32_t off = (uint32_t)((k0 + lrow) * PHA_SB + (m0 + lcol) * 2);
                LDMX4T(ath[mt], pha_hi_b + off);
                LDMX4T(atl[mt], pha_lo_b + off);
            }
            #pragma unroll
            for (int nt = 0; nt < 8; ++nt) {
                const uint32_t roff = (uint32_t)(nb + nt * 8 + b_row) * RS_SB
                                    + (uint32_t)(ks * 16) * 2 + b_koff;
                uint32_t bh[2], bl[2];
                LDMX2(bh, rs_hi_b + roff);
                LDMX2(bl, rs_lo_b + roff);
                #pragma unroll
                for (int mt = 0; mt < 2; ++mt) {
                    MMA_BF16(cB[mt][nt], ath[mt], bh[0], bh[1]);
                    MMA_BF16(cB[mt][nt], ath[mt], bl[0], bl[1]);
                    MMA_BF16(cB[mt][nt], atl[mt], bh[0], bh[1]);
                }
            }
        }

        #pragma unroll
        for (int mt = 0; mt < 2; ++mt) {
            #pragma unroll
            for (int nt = 0; nt < 8; ++nt) {
                const int col0 = base + nb + nt * 8 + 2 * tg;
                if (col0 + 1 >= K) continue;
                const int r0 = 32 * w + 16 * mt + g;
                const int r1 = r0 + 8;
                const float2 x0 = *(const float2*)(X + (size_t)r0 * K + col0);
                const float2 x1 = *(const float2*)(X + (size_t)r1 * K + col0);
                float u00 = x0.x + cB[mt][nt][0];
                float u01 = x0.y + cB[mt][nt][1];
                float u10 = x1.x + cB[mt][nt][2];
                float u11 = x1.y + cB[mt][nt][3];
                u00 = (fabsf(u00) > 0.1f) ? u00 : 0.0f;
                u01 = (fabsf(u01) > 0.1f) ? u01 : 0.0f;
                u10 = (fabsf(u10) > 0.1f) ? u10 : 0.0f;
                u11 = (fabsf(u11) > 0.1f) ? u11 : 0.0f;
                const bool a0 = (col0 < kact), a1 = (col0 + 1 < kact);
                float2 o0, o1;
                o0.x = a0 ? u00 : x0.x;  o0.y = a1 ? u01 : x0.y;
                o1.x = a0 ? u10 : x1.x;  o1.y = a1 ? u11 : x1.y;
                *(float2*)(outX + (size_t)r0 * K + col0) = o0;
                *(float2*)(outX + (size_t)r1 * K + col0) = o1;
            }
        }
    }
}

extern "C" void kernel_launch(void* const* d_in, const int* in_sizes, int n_in,
                              void* d_out, int out_size)
{
    const float* phi  = (const float*)d_in[0];
    const float* X    = (const float*)d_in[1];
    const float* Y    = (const float*)d_in[2];
    const float* step = (const float*)d_in[3];
    const int*   idx  = (const int*)d_in[4];

    const int phiN = in_sizes[0];
    const int XN   = in_sizes[1];
    const int K    = XN / NROW;

    float* outX = (float*)d_out;
    if (out_size == phiN + XN) {
        cudaMemcpyAsync(d_out, phi, (size_t)phiN * sizeof(float),
                        cudaMemcpyDeviceToDevice, 0);
        outX = (float*)d_out + phiN;
    }

    cudaFuncSetAttribute(ista_hmma_kernel,
                         cudaFuncAttributeMaxDynamicSharedMemorySize, SMEM_TOTAL);

    const int grid = (K + NT - 1) / NT;
    ista_hmma_kernel<<<grid, TPB, SMEM_TOTAL>>>(phi, X, Y, step, idx, outX, K);
}

// round 12
// speedup vs baseline: 1.2741x; 1.1456x over previous
#include <cuda_runtime.h>
#include <cuda_fp16.h>
#include <cstdint>
#include <math.h>

// phi (64,256) row-major, X (256,K), Y (64,K); k = idx+1 active columns.
constexpr int NROW = 256;
constexpr int MDIM = 64;
constexpr int NT   = 128;   // columns per CTA tile
constexpr int TPB  = 256;   // 8 warps

// ---- SMEM map (fp16 single-precision operands) ----
constexpr int PHA    = 0;        // phi [64][264] fp16 row-major (k-contig), 528B stride
constexpr int XF     = 33792;    // X FULL tile [128 cols][264 k] fp16, 528B stride (67.6KB)
constexpr int RS     = 33792;    // resid [128 cols][72] fp16, 144B stride; aliases XF
constexpr int SMEM_TOTAL = 33792 + 67584 + 128;   // 101504 -> 2 CTAs/SM

constexpr int PHA_SB = 528;
constexpr int XF_SB  = 528;     // 33 x 16B -> STS.128 & ldmatrix conflict-free (33 coprime 8)
constexpr int RS_SB  = 144;     // 9 x 16B  -> conflict-free (9 coprime 8)

__device__ __forceinline__ uint32_t smem_u32(const void* p) {
    uint32_t a;
    asm("{ .reg .u64 t; cvta.to.shared.u64 t, %1; cvt.u32.u64 %0, t; }" : "=r"(a) : "l"(p));
    return a;
}
__device__ __forceinline__ uint32_t pack_h2(float a, float b) {
    __half ha = __float2half_rn(a), hb = __float2half_rn(b);
    return (uint32_t)__half_as_ushort(ha) | ((uint32_t)__half_as_ushort(hb) << 16);
}

// mma.sync m16n8k16 row.col f32 += f16*f16 (compute_80+)
#define MMA_F16(c, a, b0, b1)                                                   \
    asm volatile("mma.sync.aligned.m16n8k16.row.col.f32.f16.f16.f32 "           \
        "{%0,%1,%2,%3}, {%4,%5,%6,%7}, {%8,%9}, {%0,%1,%2,%3};"                 \
        : "+f"((c)[0]), "+f"((c)[1]), "+f"((c)[2]), "+f"((c)[3])                \
        : "r"((a)[0]), "r"((a)[1]), "r"((a)[2]), "r"((a)[3]), "r"(b0), "r"(b1))

#define LDMX4(r, addr)                                                          \
    asm volatile("ldmatrix.sync.aligned.m8n8.x4.shared.b16 {%0,%1,%2,%3}, [%4];"\
        : "=r"((r)[0]), "=r"((r)[1]), "=r"((r)[2]), "=r"((r)[3]) : "r"(addr))
#define LDMX4T(r, addr)                                                         \
    asm volatile("ldmatrix.sync.aligned.m8n8.x4.trans.shared.b16 {%0,%1,%2,%3}, [%4];" \
        : "=r"((r)[0]), "=r"((r)[1]), "=r"((r)[2]), "=r"((r)[3]) : "r"(addr))
#define LDMX2(r, addr)                                                          \
    asm volatile("ldmatrix.sync.aligned.m8n8.x2.shared.b16 {%0,%1}, [%2];"      \
        : "=r"((r)[0]), "=r"((r)[1]) : "r"(addr))

extern __shared__ char smem_g[];

__global__ __launch_bounds__(TPB, 2)
void ista_hmma_kernel(const float* __restrict__ phi,
                      const float* __restrict__ X,
                      const float* __restrict__ Y,
                      const float* __restrict__ step,
                      const int*   __restrict__ idxp,
                      float*       __restrict__ outX,
                      int K)
{
    char* smem = smem_g;
    const int tid  = threadIdx.x;
    const int w    = tid >> 5;
    const int lane = tid & 31;
    const int g    = lane >> 2;
    const int tg   = lane & 3;
    const int base = blockIdx.x * NT;
    const int kact = *idxp + 1;

    // ---------------- passthrough tiles ----------------
    if (base >= kact) {
        const int col = base + (tid & 127);
        if (col < K) {
            for (int n = (tid >> 7); n < NROW; n += 2)
                outX[(size_t)n * K + col] = X[(size_t)n * K + col];
        }
        return;
    }

    const float s = *step;

    uint32_t* pha16u = (uint32_t*)(smem + PHA);
    uint16_t* rs16   = (uint16_t*)(smem + RS);

    const uint32_t pha_b = smem_u32(smem + PHA);
    const uint32_t xf_b  = smem_u32(smem + XF);
    const uint32_t rs_b  = smem_u32(smem + RS);

    // ---------------- stage phi (fp16, native row-major) ----------------
    for (int it = tid; it < MDIM * 128; it += TPB) {
        const int m = it >> 7, kp = it & 127;
        const float2 v = *(const float2*)(phi + m * NROW + 2 * kp);
        pha16u[m * 132 + kp] = pack_h2(v.x, v.y);
    }

    // ---------------- stage FULL X tile (fp16), conflict-free STS.128 ----------------
    // thread: col = tid&127, k-half = tid>>7 (128 rows -> 16 quads of 8 fp16)
    {
        const int scol = tid & 127;
        const int half = tid >> 7;
        int gc = base + scol; gc = (gc < K) ? gc : (K - 1);
        #pragma unroll 4
        for (int q = 0; q < 16; ++q) {
            const int r0 = half * 128 + q * 8;
            uint32_t u[4];
            #pragma unroll
            for (int j = 0; j < 4; ++j) {
                const float a = X[(size_t)(r0 + 2 * j) * K + gc];
                const float b = X[(size_t)(r0 + 2 * j + 1) * K + gc];
                u[j] = pack_h2(a, b);
            }
            *(uint4*)(smem + XF + scol * XF_SB + (half * 16 + q) * 16)
                = make_uint4(u[0], u[1], u[2], u[3]);
        }
    }
    __syncthreads();

    // ================= GEMM A: R(64x128) = phi . Xtile, one monolithic loop =================
    const int mbase = 32 * (w & 1);
    const int nbase = 32 * (w >> 1);
    float cA[2][4][4];
    #pragma unroll
    for (int mt = 0; mt < 2; ++mt)
        #pragma unroll
        for (int nt = 0; nt < 4; ++nt)
            #pragma unroll
            for (int q = 0; q < 4; ++q) cA[mt][nt][q] = 0.0f;

    const uint32_t a_row_off = (uint32_t)(lane & 15) * PHA_SB + (uint32_t)((lane >> 4) << 3) * 2;
    const uint32_t b_row     = (uint32_t)(lane & 7);
    const uint32_t b_koff    = (uint32_t)(((lane >> 3) & 1) << 4);   // 16B (k+8 group)

    // Y prefetch: consumed after the 16-k-step MMA loop (long cover)
    float2 yv[2][4][2];
    #pragma unroll
    for (int mt = 0; mt < 2; ++mt)
        #pragma unroll
        for (int nt = 0; nt < 4; ++nt) {
            const int nloc = nbase + nt * 8 + 2 * tg;
            int col0 = base + nloc; col0 = (col0 < K - 1) ? col0 : (K - 2);
            const int m0 = mbase + 16 * mt + g;
            yv[mt][nt][0] = *(const float2*)(Y + (size_t)m0 * K + col0);
            yv[mt][nt][1] = *(const float2*)(Y + (size_t)(m0 + 8) * K + col0);
        }

    #pragma unroll 4
    for (int ks = 0; ks < 16; ++ks) {
        const int k0 = ks * 16;
        uint32_t a[2][4];
        #pragma unroll
        for (int mt = 0; mt < 2; ++mt) {
            const uint32_t aoff = (uint32_t)(mbase + 16 * mt) * PHA_SB
                                + (uint32_t)k0 * 2 + a_row_off;
            LDMX4(a[mt], pha_b + aoff);
        }
        #pragma unroll
        for (int nt = 0; nt < 4; ++nt) {
            const uint32_t roff = (uint32_t)(nbase + nt * 8 + b_row) * XF_SB
                                + (uint32_t)k0 * 2 + b_koff;
            uint32_t b[2];
            LDMX2(b, xf_b + roff);
            #pragma unroll
            for (int mt = 0; mt < 2; ++mt)
                MMA_F16(cA[mt][nt], a[mt], b[0], b[1]);
        }
    }
    __syncthreads();   // XF consumed before RS aliases it

    // ---- epilogue A: r = s*(y - R) -> fp16 -> Rs[n][m] ----
    #pragma unroll
    for (int mt = 0; mt < 2; ++mt)
        #pragma unroll
        for (int nt = 0; nt < 4; ++nt) {
            const int nloc = nbase + nt * 8 + 2 * tg;
            const int m0 = mbase + 16 * mt + g, m1 = m0 + 8;
            const float2 y0 = yv[mt][nt][0], y1 = yv[mt][nt][1];
            rs16[nloc * 72 + m0]       = __half_as_ushort(__float2half_rn(s * (y0.x - cA[mt][nt][0])));
            rs16[(nloc + 1) * 72 + m0] = __half_as_ushort(__float2half_rn(s * (y0.y - cA[mt][nt][1])));
            rs16[nloc * 72 + m1]       = __half_as_ushort(__float2half_rn(s * (y1.x - cA[mt][nt][2])));
            rs16[(nloc + 1) * 72 + m1] = __half_as_ushort(__float2half_rn(s * (y1.y - cA[mt][nt][3])));
        }
    __syncthreads();

    // ================= GEMM B: corr(256x128) = phiT . R, K=64 =================
    const int lrow = (lane & 7) + ((lane & 16) >> 1);
    const int lcol = (lane & 8);

    #pragma unroll 1
    for (int pass = 0; pass < 2; ++pass) {
        const int nb = pass * 64;
        float cB[2][8][4];
        #pragma unroll
        for (int mt = 0; mt < 2; ++mt)
            #pragma unroll
            for (int nt = 0; nt < 8; ++nt)
                #pragma unroll
                for (int q = 0; q < 4; ++q) cB[mt][nt][q] = 0.0f;

        #pragma unroll
        for (int ks = 0; ks < 4; ++ks) {
            const int k0 = ks * 16;
            uint32_t at[2][4];
            #pragma unroll
            for (int mt = 0; mt < 2; ++mt) {
                const int m0 = 32 * w + 16 * mt;
                const uint32_t off = (uint32_t)((k0 + lrow) * PHA_SB + (m0 + lcol) * 2);
                LDMX4T(at[mt], pha_b + off);
            }
            #pragma unroll
            for (int nt = 0; nt < 8; ++nt) {
                const uint32_t roff = (uint32_t)(nb + nt * 8 + b_row) * RS_SB
                                    + (uint32_t)k0 * 2 + b_koff;
                uint32_t b[2];
                LDMX2(b, rs_b + roff);
                #pragma unroll
                for (int mt = 0; mt < 2; ++mt)
                    MMA_F16(cB[mt][nt], at[mt], b[0], b[1]);
            }
        }

        // ---- epilogue B: out = thresh(X + corr), passthrough beyond kact ----
        #pragma unroll
        for (int mt = 0; mt < 2; ++mt) {
            #pragma unroll
            for (int nt = 0; nt < 8; ++nt) {
                const int col0 = base + nb + nt * 8 + 2 * tg;
                if (col0 + 1 >= K) continue;
                const int r0 = 32 * w + 16 * mt + g;
                const int r1 = r0 + 8;
                const float2 x0 = *(const float2*)(X + (size_t)r0 * K + col0);
                const float2 x1 = *(const float2*)(X + (size_t)r1 * K + col0);
                float u00 = x0.x + cB[mt][nt][0];
                float u01 = x0.y + cB[mt][nt][1];
                float u10 = x1.x + cB[mt][nt][2];
                float u11 = x1.y + cB[mt][nt][3];
                u00 = (fabsf(u00) > 0.1f) ? u00 : 0.0f;
                u01 = (fabsf(u01) > 0.1f) ? u01 : 0.0f;
                u10 = (fabsf(u10) > 0.1f) ? u10 : 0.0f;
                u11 = (fabsf(u11) > 0.1f) ? u11 : 0.0f;
                const bool a0 = (col0 < kact), a1 = (col0 + 1 < kact);
                float2 o0, o1;
                o0.x = a0 ? u00 : x0.x;  o0.y = a1 ? u01 : x0.y;
                o1.x = a0 ? u10 : x1.x;  o1.y = a1 ? u11 : x1.y;
                *(float2*)(outX + (size_t)r0 * K + col0) = o0;
                *(float2*)(outX + (size_t)r1 * K + col0) = o1;
            }
        }
    }
}

extern "C" void kernel_launch(void* const* d_in, const int* in_sizes, int n_in,
                              void* d_out, int out_size)
{
    const float* phi  = (const float*)d_in[0];
    const float* X    = (const float*)d_in[1];
    const float* Y    = (const float*)d_in[2];
    const float* step = (const float*)d_in[3];
    const int*   idx  = (const int*)d_in[4];

    const int phiN = in_sizes[0];
    const int XN   = in_sizes[1];
    const int K    = XN / NROW;

    float* outX = (float*)d_out;
    if (out_size == phiN + XN) {
        cudaMemcpyAsync(d_out, phi, (size_t)phiN * sizeof(float),
                        cudaMemcpyDeviceToDevice, 0);
        outX = (float*)d_out + phiN;
    }

    cudaFuncSetAttribute(ista_hmma_kernel,
                         cudaFuncAttributeMaxDynamicSharedMemorySize, SMEM_TOTAL);

    const int grid = (K + NT - 1) / NT;
    ista_hmma_kernel<<<grid, TPB, SMEM_TOTAL>>>(phi, X, Y, step, idx, outX, K);
}

// round 13
// speedup vs baseline: 1.4573x; 1.1438x over previous
#include <cuda_runtime.h>
#include <cuda_fp16.h>
#include <cstdint>
#include <math.h>

// phi (64,256) row-major, X (256,K), Y (64,K); k = idx+1 active columns.
constexpr int NROW = 256;
constexpr int MDIM = 64;
constexpr int NT   = 64;    // columns per CTA tile (halved -> 3 CTAs/SM)
constexpr int TPB  = 256;   // 8 warps

// ---- SMEM map (fp16 operands) ----
constexpr int PHA = 0;        // phi [64][264] fp16 row-major (k-contig), 528B stride
constexpr int XF  = 33792;    // X tile [64 cols][264 k] fp16, 528B stride (33.8KB)
constexpr int RS  = 33792;    // resid [64 cols][72] fp16, 144B stride; aliases XF
constexpr int SMEM_TOTAL = 33792 + 33792 + 128;   // 67712 -> 3 CTAs/SM

constexpr int PHA_SB = 528;
constexpr int XF_SB  = 528;   // 33 x 16B -> STS.128 & ldmatrix conflict-free (33 coprime 8)
constexpr int RS_SB  = 144;   // 9 x 16B  -> conflict-free

__device__ __forceinline__ uint32_t smem_u32(const void* p) {
    uint32_t a;
    asm("{ .reg .u64 t; cvta.to.shared.u64 t, %1; cvt.u32.u64 %0, t; }" : "=r"(a) : "l"(p));
    return a;
}
__device__ __forceinline__ uint32_t pack_h2(float a, float b) {
    __half ha = __float2half_rn(a), hb = __float2half_rn(b);
    return (uint32_t)__half_as_ushort(ha) | ((uint32_t)__half_as_ushort(hb) << 16);
}

#define MMA_F16(c, a, b0, b1)                                                   \
    asm volatile("mma.sync.aligned.m16n8k16.row.col.f32.f16.f16.f32 "           \
        "{%0,%1,%2,%3}, {%4,%5,%6,%7}, {%8,%9}, {%0,%1,%2,%3};"                 \
        : "+f"((c)[0]), "+f"((c)[1]), "+f"((c)[2]), "+f"((c)[3])                \
        : "r"((a)[0]), "r"((a)[1]), "r"((a)[2]), "r"((a)[3]), "r"(b0), "r"(b1))

#define LDMX4(r, addr)                                                          \
    asm volatile("ldmatrix.sync.aligned.m8n8.x4.shared.b16 {%0,%1,%2,%3}, [%4];"\
        : "=r"((r)[0]), "=r"((r)[1]), "=r"((r)[2]), "=r"((r)[3]) : "r"(addr))
#define LDMX4T(r, addr)                                                         \
    asm volatile("ldmatrix.sync.aligned.m8n8.x4.trans.shared.b16 {%0,%1,%2,%3}, [%4];" \
        : "=r"((r)[0]), "=r"((r)[1]), "=r"((r)[2]), "=r"((r)[3]) : "r"(addr))
#define LDMX2(r, addr)                                                          \
    asm volatile("ldmatrix.sync.aligned.m8n8.x2.shared.b16 {%0,%1}, [%2];"      \
        : "=r"((r)[0]), "=r"((r)[1]) : "r"(addr))

extern __shared__ char smem_g[];

__global__ __launch_bounds__(TPB, 3)
void ista_hmma_kernel(const float* __restrict__ phi,
                      const float* __restrict__ X,
                      const float* __restrict__ Y,
                      const float* __restrict__ step,
                      const int*   __restrict__ idxp,
                      float*       __restrict__ outX,
                      int K)
{
    char* smem = smem_g;
    const int tid  = threadIdx.x;
    const int w    = tid >> 5;
    const int lane = tid & 31;
    const int g    = lane >> 2;
    const int tg   = lane & 3;
    const int base = blockIdx.x * NT;
    const int kact = *idxp + 1;

    // ---------------- passthrough tiles ----------------
    if (base >= kact) {
        const int col = base + (tid & 63);
        if (col < K) {
            for (int n = (tid >> 6); n < NROW; n += 4)
                outX[(size_t)n * K + col] = X[(size_t)n * K + col];
        }
        return;
    }

    const float s = *step;

    uint32_t* pha16u = (uint32_t*)(smem + PHA);
    uint16_t* rs16   = (uint16_t*)(smem + RS);

    const uint32_t pha_b = smem_u32(smem + PHA);
    const uint32_t xf_b  = smem_u32(smem + XF);
    const uint32_t rs_b  = smem_u32(smem + RS);

    // ---------------- stage phi (fp16, native row-major) ----------------
    for (int it = tid; it < MDIM * 128; it += TPB) {
        const int m = it >> 7, kp = it & 127;
        const float2 v = *(const float2*)(phi + m * NROW + 2 * kp);
        pha16u[m * 132 + kp] = pack_h2(v.x, v.y);
    }

    // ---------------- stage X tile (fp16), conflict-free STS.128 ----------------
    // thread: col = tid&63, k-quarter = tid>>6 (64 rows -> 8 quads of 8 fp16)
    {
        const int scol = tid & 63;
        const int kq   = tid >> 6;
        int gc = base + scol; gc = (gc < K) ? gc : (K - 1);
        #pragma unroll 2
        for (int q = 0; q < 8; ++q) {
            const int r0 = kq * 64 + q * 8;
            uint32_t u[4];
            #pragma unroll
            for (int j = 0; j < 4; ++j) {
                const float a = X[(size_t)(r0 + 2 * j) * K + gc];
                const float b = X[(size_t)(r0 + 2 * j + 1) * K + gc];
                u[j] = pack_h2(a, b);
            }
            *(uint4*)(smem + XF + scol * XF_SB + (kq * 8 + q) * 16)
                = make_uint4(u[0], u[1], u[2], u[3]);
        }
    }
    __syncthreads();

    // ================= GEMM A: R(64x64) = phi . Xtile =================
    // 8 warps: 2m x 4n -> warp tile m32 x n16
    const int mbase = 32 * (w & 1);
    const int nbase = 16 * (w >> 1);
    float cA[2][2][4];
    #pragma unroll
    for (int mt = 0; mt < 2; ++mt)
        #pragma unroll
        for (int nt = 0; nt < 2; ++nt)
            #pragma unroll
            for (int q = 0; q < 4; ++q) cA[mt][nt][q] = 0.0f;

    const uint32_t a_row_off = (uint32_t)(lane & 15) * PHA_SB + (uint32_t)((lane >> 4) << 3) * 2;
    const uint32_t b_row     = (uint32_t)(lane & 7);
    const uint32_t b_koff    = (uint32_t)(((lane >> 3) & 1) << 4);

    #pragma unroll 4
    for (int ks = 0; ks < 16; ++ks) {
        const int k0 = ks * 16;
        uint32_t a[2][4];
        #pragma unroll
        for (int mt = 0; mt < 2; ++mt) {
            const uint32_t aoff = (uint32_t)(mbase + 16 * mt) * PHA_SB
                                + (uint32_t)k0 * 2 + a_row_off;
            LDMX4(a[mt], pha_b + aoff);
        }
        #pragma unroll
        for (int nt = 0; nt < 2; ++nt) {
            const uint32_t roff = (uint32_t)(nbase + nt * 8 + b_row) * XF_SB
                                + (uint32_t)k0 * 2 + b_koff;
            uint32_t b[2];
            LDMX2(b, xf_b + roff);
            #pragma unroll
            for (int mt = 0; mt < 2; ++mt)
                MMA_F16(cA[mt][nt], a[mt], b[0], b[1]);
        }
    }
    __syncthreads();   // XF consumed before RS aliases it

    // ---- epilogue A: r = s*(y - R) -> fp16 -> Rs[n][m] (Y read direct) ----
    #pragma unroll
    for (int mt = 0; mt < 2; ++mt)
        #pragma unroll
        for (int nt = 0; nt < 2; ++nt) {
            const int nloc = nbase + nt * 8 + 2 * tg;
            int col0 = base + nloc; col0 = (col0 < K - 1) ? col0 : (K - 2);
            const int m0 = mbase + 16 * mt + g, m1 = m0 + 8;
            const float2 y0 = *(const float2*)(Y + (size_t)m0 * K + col0);
            const float2 y1 = *(const float2*)(Y + (size_t)m1 * K + col0);
            rs16[nloc * 72 + m0]       = __half_as_ushort(__float2half_rn(s * (y0.x - cA[mt][nt][0])));
            rs16[(nloc + 1) * 72 + m0] = __half_as_ushort(__float2half_rn(s * (y0.y - cA[mt][nt][1])));
            rs16[nloc * 72 + m1]       = __half_as_ushort(__float2half_rn(s * (y1.x - cA[mt][nt][2])));
            rs16[(nloc + 1) * 72 + m1] = __half_as_ushort(__float2half_rn(s * (y1.y - cA[mt][nt][3])));
        }
    __syncthreads();

    // ================= GEMM B: corr(256x64) = phiT . R, K=64, 2 passes of n32 =================
    const int lrow = (lane & 7) + ((lane & 16) >> 1);
    const int lcol = (lane & 8);

    #pragma unroll 1
    for (int pass = 0; pass < 2; ++pass) {
        const int nb = pass * 32;
        float cB[2][4][4];
        #pragma unroll
        for (int mt = 0; mt < 2; ++mt)
            #pragma unroll
            for (int nt = 0; nt < 4; ++nt)
                #pragma unroll
                for (int q = 0; q < 4; ++q) cB[mt][nt][q] = 0.0f;

        #pragma unroll
        for (int ks = 0; ks < 4; ++ks) {
            const int k0 = ks * 16;
            uint32_t at[2][4];
            #pragma unroll
            for (int mt = 0; mt < 2; ++mt) {
                const int m0 = 32 * w + 16 * mt;
                const uint32_t off = (uint32_t)((k0 + lrow) * PHA_SB + (m0 + lcol) * 2);
                LDMX4T(at[mt], pha_b + off);
            }
            #pragma unroll
            for (int nt = 0; nt < 4; ++nt) {
                const uint32_t roff = (uint32_t)(nb + nt * 8 + b_row) * RS_SB
                                    + (uint32_t)k0 * 2 + b_koff;
                uint32_t b[2];
                LDMX2(b, rs_b + roff);
                #pragma unroll
                for (int mt = 0; mt < 2; ++mt)
                    MMA_F16(cB[mt][nt], at[mt], b[0], b[1]);
            }
        }

        // ---- epilogue B: out = thresh(X + corr), passthrough beyond kact ----
        #pragma unroll
        for (int mt = 0; mt < 2; ++mt) {
            #pragma unroll
            for (int nt = 0; nt < 4; ++nt) {
                const int col0 = base + nb + nt * 8 + 2 * tg;
                if (col0 + 1 >= K) continue;
                const int r0 = 32 * w + 16 * mt + g;
                const int r1 = r0 + 8;
                const float2 x0 = *(const float2*)(X + (size_t)r0 * K + col0);
                const float2 x1 = *(const float2*)(X + (size_t)r1 * K + col0);
                float u00 = x0.x + cB[mt][nt][0];
                float u01 = x0.y + cB[mt][nt][1];
                float u10 = x1.x + cB[mt][nt][2];
                float u11 = x1.y + cB[mt][nt][3];
                u00 = (fabsf(u00) > 0.1f) ? u00 : 0.0f;
                u01 = (fabsf(u01) > 0.1f) ? u01 : 0.0f;
                u10 = (fabsf(u10) > 0.1f) ? u10 : 0.0f;
                u11 = (fabsf(u11) > 0.1f) ? u11 : 0.0f;
                const bool a0 = (col0 < kact), a1 = (col0 + 1 < kact);
                float2 o0, o1;
                o0.x = a0 ? u00 : x0.x;  o0.y = a1 ? u01 : x0.y;
                o1.x = a0 ? u10 : x1.x;  o1.y = a1 ? u11 : x1.y;
                *(float2*)(outX + (size_t)r0 * K + col0) = o0;
                *(float2*)(outX + (size_t)r1 * K + col0) = o1;
            }
        }
    }
}

extern "C" void kernel_launch(void* const* d_in, const int* in_sizes, int n_in,
                              void* d_out, int out_size)
{
    const float* phi  = (const float*)d_in[0];
    const float* X    = (const float*)d_in[1];
    const float* Y    = (const float*)d_in[2];
    const float* step = (const float*)d_in[3];
    const int*   idx  = (const int*)d_in[4];

    const int phiN = in_sizes[0];
    const int XN   = in_sizes[1];
    const int K    = XN / NROW;

    float* outX = (float*)d_out;
    if (out_size == phiN + XN) {
        cudaMemcpyAsync(d_out, phi, (size_t)phiN * sizeof(float),
                        cudaMemcpyDeviceToDevice, 0);
        outX = (float*)d_out + phiN;
    }

    cudaFuncSetAttribute(ista_hmma_kernel,
                         cudaFuncAttributeMaxDynamicSharedMemorySize, SMEM_TOTAL);

    const int grid = (K + NT - 1) / NT;
    ista_hmma_kernel<<<grid, TPB, SMEM_TOTAL>>>(phi, X, Y, step, idx, outX, K);
}

// round 14
// speedup vs baseline: 1.5432x; 1.0589x over previous
#include <cuda_runtime.h>
#include <cuda_fp16.h>
#include <cstdint>
#include <math.h>

// phi (64,256) row-major, X (256,K), Y (64,K); k = idx+1 active columns.
constexpr int NROW = 256;
constexpr int MDIM = 64;
constexpr int NT   = 64;    // columns per CTA tile
constexpr int TPB  = 256;   // 8 warps; 4 CTAs/SM

// ---- SMEM map (fp16 operands) ----
constexpr int PHA = 0;        // phi [64][264] fp16 row-major (k-contig), 528B stride
constexpr int XF  = 33792;    // X half-tile [64 cols][128 k] fp16, 272B stride (17.4KB)
constexpr int RS  = 33792;    // resid [64 cols][72] fp16, 144B stride; aliases XF
constexpr int SMEM_TOTAL = 33792 + 17408 + 128;   // 51328 -> 4 CTAs/SM

constexpr int PHA_SB = 528;
constexpr int XF_SB  = 272;   // 17 x 16B -> STS.128 & ldmatrix conflict-free (17 coprime 8)
constexpr int RS_SB  = 144;   // 9 x 16B  -> conflict-free

__device__ __forceinline__ uint32_t smem_u32(const void* p) {
    uint32_t a;
    asm("{ .reg .u64 t; cvta.to.shared.u64 t, %1; cvt.u32.u64 %0, t; }" : "=r"(a) : "l"(p));
    return a;
}
__device__ __forceinline__ uint32_t pack_h2(float a, float b) {
    __half ha = __float2half_rn(a), hb = __float2half_rn(b);
    return (uint32_t)__half_as_ushort(ha) | ((uint32_t)__half_as_ushort(hb) << 16);
}

#define MMA_F16(c, a, b0, b1)                                                   \
    asm volatile("mma.sync.aligned.m16n8k16.row.col.f32.f16.f16.f32 "           \
        "{%0,%1,%2,%3}, {%4,%5,%6,%7}, {%8,%9}, {%0,%1,%2,%3};"                 \
        : "+f"((c)[0]), "+f"((c)[1]), "+f"((c)[2]), "+f"((c)[3])                \
        : "r"((a)[0]), "r"((a)[1]), "r"((a)[2]), "r"((a)[3]), "r"(b0), "r"(b1))

#define LDMX4(r, addr)                                                          \
    asm volatile("ldmatrix.sync.aligned.m8n8.x4.shared.b16 {%0,%1,%2,%3}, [%4];"\
        : "=r"((r)[0]), "=r"((r)[1]), "=r"((r)[2]), "=r"((r)[3]) : "r"(addr))
#define LDMX4T(r, addr)                                                         \
    asm volatile("ldmatrix.sync.aligned.m8n8.x4.trans.shared.b16 {%0,%1,%2,%3}, [%4];" \
        : "=r"((r)[0]), "=r"((r)[1]), "=r"((r)[2]), "=r"((r)[3]) : "r"(addr))
#define LDMX2(r, addr)                                                          \
    asm volatile("ldmatrix.sync.aligned.m8n8.x2.shared.b16 {%0,%1}, [%2];"      \
        : "=r"((r)[0]), "=r"((r)[1]) : "r"(addr))

extern __shared__ char smem_g[];

__global__ __launch_bounds__(TPB, 4)
void ista_hmma_kernel(const float* __restrict__ phi,
                      const float* __restrict__ X,
                      const float* __restrict__ Y,
                      const float* __restrict__ step,
                      const int*   __restrict__ idxp,
                      float*       __restrict__ outX,
                      int K)
{
    char* smem = smem_g;
    const int tid  = threadIdx.x;
    const int w    = tid >> 5;
    const int lane = tid & 31;
    const int g    = lane >> 2;
    const int tg   = lane & 3;
    const int base = blockIdx.x * NT;
    const int kact = *idxp + 1;

    // ---------------- passthrough tiles ----------------
    if (base >= kact) {
        const int col = base + (tid & 63);
        if (col < K) {
            for (int n = (tid >> 6); n < NROW; n += 4)
                outX[(size_t)n * K + col] = X[(size_t)n * K + col];
        }
        return;
    }

    const float s = *step;

    uint32_t* pha16u = (uint32_t*)(smem + PHA);
    uint16_t* rs16   = (uint16_t*)(smem + RS);

    const uint32_t pha_b = smem_u32(smem + PHA);
    const uint32_t xf_b  = smem_u32(smem + XF);
    const uint32_t rs_b  = smem_u32(smem + RS);

    // ---------------- stage phi (fp16, native row-major) ----------------
    for (int it = tid; it < MDIM * 128; it += TPB) {
        const int m = it >> 7, kp = it & 127;
        const float2 v = *(const float2*)(phi + m * NROW + 2 * kp);
        pha16u[m * 132 + kp] = pack_h2(v.x, v.y);
    }

    // staging geometry: col = tid&63, k-quarter = tid>>6 (32 rows = 4 quads each)
    const int scol = tid & 63;
    const int kq   = tid >> 6;
    int gc = base + scol; gc = (gc < K) ? gc : (K - 1);

    // ================= GEMM A: R(64x64) = phi . Xtile, 2 k-halves =================
    const int mbase = 32 * (w & 1);
    const int nbase = 16 * (w >> 1);
    float cA[2][2][4];
    #pragma unroll
    for (int mt = 0; mt < 2; ++mt)
        #pragma unroll
        for (int nt = 0; nt < 2; ++nt)
            #pragma unroll
            for (int q = 0; q < 4; ++q) cA[mt][nt][q] = 0.0f;

    const uint32_t a_row_off = (uint32_t)(lane & 15) * PHA_SB + (uint32_t)((lane >> 4) << 3) * 2;
    const uint32_t b_row     = (uint32_t)(lane & 7);
    const uint32_t b_koff    = (uint32_t)(((lane >> 3) & 1) << 4);

    #pragma unroll 1
    for (int half = 0; half < 2; ++half) {
        // stage this k-half of X (fp16, STS.128 conflict-free: 17x16B stride)
        #pragma unroll
        for (int q = 0; q < 4; ++q) {
            const int r0 = half * 128 + kq * 32 + q * 8;
            uint32_t u[4];
            #pragma unroll
            for (int j = 0; j < 4; ++j) {
                const float a = X[(size_t)(r0 + 2 * j) * K + gc];
                const float b = X[(size_t)(r0 + 2 * j + 1) * K + gc];
                u[j] = pack_h2(a, b);
            }
            *(uint4*)(smem + XF + scol * XF_SB + (kq * 4 + q) * 16)
                = make_uint4(u[0], u[1], u[2], u[3]);
        }
        __syncthreads();

        #pragma unroll 4
        for (int ks = 0; ks < 8; ++ks) {
            const int k0g = half * 128 + ks * 16;   // phi k (global)
            const int k0l = ks * 16;                // XF k (local to half)
            uint32_t a[2][4];
            #pragma unroll
            for (int mt = 0; mt < 2; ++mt) {
                const uint32_t aoff = (uint32_t)(mbase + 16 * mt) * PHA_SB
                                    + (uint32_t)k0g * 2 + a_row_off;
                LDMX4(a[mt], pha_b + aoff);
            }
            #pragma unroll
            for (int nt = 0; nt < 2; ++nt) {
                const uint32_t roff = (uint32_t)(nbase + nt * 8 + b_row) * XF_SB
                                    + (uint32_t)k0l * 2 + b_koff;
                uint32_t b[2];
                LDMX2(b, xf_b + roff);
                #pragma unroll
                for (int mt = 0; mt < 2; ++mt)
                    MMA_F16(cA[mt][nt], a[mt], b[0], b[1]);
            }
        }
        __syncthreads();   // buffer consumed before restage / RS alias
    }

    // ---- epilogue A: r = s*(y - R) -> fp16 -> Rs[n][m] (Y read direct) ----
    #pragma unroll
    for (int mt = 0; mt < 2; ++mt)
        #pragma unroll
        for (int nt = 0; nt < 2; ++nt) {
            const int nloc = nbase + nt * 8 + 2 * tg;
            int col0 = base + nloc; col0 = (col0 < K - 1) ? col0 : (K - 2);
            const int m0 = mbase + 16 * mt + g, m1 = m0 + 8;
            const float2 y0 = *(const float2*)(Y + (size_t)m0 * K + col0);
            const float2 y1 = *(const float2*)(Y + (size_t)m1 * K + col0);
            rs16[nloc * 72 + m0]       = __half_as_ushort(__float2half_rn(s * (y0.x - cA[mt][nt][0])));
            rs16[(nloc + 1) * 72 + m0] = __half_as_ushort(__float2half_rn(s * (y0.y - cA[mt][nt][1])));
            rs16[nloc * 72 + m1]       = __half_as_ushort(__float2half_rn(s * (y1.x - cA[mt][nt][2])));
            rs16[(nloc + 1) * 72 + m1] = __half_as_ushort(__float2half_rn(s * (y1.y - cA[mt][nt][3])));
        }
    __syncthreads();

    // ================= GEMM B: corr(256x64) = phiT . R, K=64, 4 passes of n16 =================
    const int lrow = (lane & 7) + ((lane & 16) >> 1);
    const int lcol = (lane & 8);

    #pragma unroll 1
    for (int pass = 0; pass < 4; ++pass) {
        const int nb = pass * 16;
        float cB[2][2][4];
        #pragma unroll
        for (int mt = 0; mt < 2; ++mt)
            #pragma unroll
            for (int nt = 0; nt < 2; ++nt)
                #pragma unroll
                for (int q = 0; q < 4; ++q) cB[mt][nt][q] = 0.0f;

        #pragma unroll
        for (int ks = 0; ks < 4; ++ks) {
            const int k0 = ks * 16;
            uint32_t at[2][4];
            #pragma unroll
            for (int mt = 0; mt < 2; ++mt) {
                const int m0 = 32 * w + 16 * mt;
                const uint32_t off = (uint32_t)((k0 + lrow) * PHA_SB + (m0 + lcol) * 2);
                LDMX4T(at[mt], pha_b + off);
            }
            #pragma unroll
            for (int nt = 0; nt < 2; ++nt) {
                const uint32_t roff = (uint32_t)(nb + nt * 8 + b_row) * RS_SB
                                    + (uint32_t)k0 * 2 + b_koff;
                uint32_t b[2];
                LDMX2(b, rs_b + roff);
                #pragma unroll
                for (int mt = 0; mt < 2; ++mt)
                    MMA_F16(cB[mt][nt], at[mt], b[0], b[1]);
            }
        }

        // ---- epilogue B: out = thresh(X + corr), passthrough beyond kact ----
        #pragma unroll
        for (int mt = 0; mt < 2; ++mt) {
            #pragma unroll
            for (int nt = 0; nt < 2; ++nt) {
                const int col0 = base + nb + nt * 8 + 2 * tg;
                if (col0 + 1 >= K) continue;
                const int r0 = 32 * w + 16 * mt + g;
                const int r1 = r0 + 8;
                const float2 x0 = *(const float2*)(X + (size_t)r0 * K + col0);
                const float2 x1 = *(const float2*)(X + (size_t)r1 * K + col0);
                float u00 = x0.x + cB[mt][nt][0];
                float u01 = x0.y + cB[mt][nt][1];
                float u10 = x1.x + cB[mt][nt][2];
                float u11 = x1.y + cB[mt][nt][3];
                u00 = (fabsf(u00) > 0.1f) ? u00 : 0.0f;
                u01 = (fabsf(u01) > 0.1f) ? u01 : 0.0f;
                u10 = (fabsf(u10) > 0.1f) ? u10 : 0.0f;
                u11 = (fabsf(u11) > 0.1f) ? u11 : 0.0f;
                const bool a0 = (col0 < kact), a1 = (col0 + 1 < kact);
                float2 o0, o1;
                o0.x = a0 ? u00 : x0.x;  o0.y = a1 ? u01 : x0.y;
                o1.x = a0 ? u10 : x1.x;  o1.y = a1 ? u11 : x1.y;
                *(float2*)(outX + (size_t)r0 * K + col0) = o0;
                *(float2*)(outX + (size_t)r1 * K + col0) = o1;
            }
        }
    }
}

extern "C" void kernel_launch(void* const* d_in, const int* in_sizes, int n_in,
                              void* d_out, int out_size)
{
    const float* phi  = (const float*)d_in[0];
    const float* X    = (const float*)d_in[1];
    const float* Y    = (const float*)d_in[2];
    const float* step = (const float*)d_in[3];
    const int*   idx  = (const int*)d_in[4];

    const int phiN = in_sizes[0];
    const int XN   = in_sizes[1];
    const int K    = XN / NROW;

    float* outX = (float*)d_out;
    if (out_size == phiN + XN) {
        cudaMemcpyAsync(d_out, phi, (size_t)phiN * sizeof(float),
                        cudaMemcpyDeviceToDevice, 0);
        outX = (float*)d_out + phiN;
    }

    cudaFuncSetAttribute(ista_hmma_kernel,
                         cudaFuncAttributeMaxDynamicSharedMemorySize, SMEM_TOTAL);

    const int grid = (K + NT - 1) / NT;
    ista_hmma_kernel<<<grid, TPB, SMEM_TOTAL>>>(phi, X, Y, step, idx, outX, K);
}